// round 2
// baseline (speedup 1.0000x reference)
#include <cuda_runtime.h>

#define TT     32768
#define HID    100
#define DIN    300
#define G4     400
#define CH     64                 // chaser chunk (timesteps)
#define NCHUNK (TT / CH)          // 512
#define NCHASE 8
#define P0CH   16                 // layer0 progress publish interval

// ---------------- scratch (static device allocations; no cudaMalloc) -------
__device__ float g_xp0[TT * G4];          // 52.4 MB: input projection, layer 0
__device__ float g_xp1[TT * G4];          // 52.4 MB: input projection, layer 1
__device__ float g_h0[TT * HID];          // 13.1 MB: layer-0 hidden sequence
__device__ float g_h1[TT * HID];          // 13.1 MB: layer-1 hidden sequence
__device__ float g_WcT[DIN * G4];         // fused (W_ih_l0 @ W_inp), transposed [k][j]
__device__ float g_bc[G4];                // fused bias for layer-0 gates
__device__ float g_WoutT[HID * DIN];      // W_out transposed [k][d]
__device__ volatile int g_prog0;          // layer-0 progress (steps completed)
__device__ volatile int g_flag1[NCHUNK];  // xp1 chunk-ready flags

typedef unsigned long long u64;

// ---------------- f32x2 packed-FMA helpers (Blackwell FFMA2) ---------------
__device__ __forceinline__ u64 ffma2(u64 a, u64 b, u64 c) {
    u64 d;
    asm("fma.rn.f32x2 %0, %1, %2, %3;" : "=l"(d) : "l"(a), "l"(b), "l"(c));
    return d;
}
__device__ __forceinline__ u64 packf2(float lo, float hi) {
    u64 v;
    asm("mov.b64 %0, {%1, %2};" : "=l"(v) : "f"(lo), "f"(hi));
    return v;
}
__device__ __forceinline__ void unpack2(u64 v, float& lo, float& hi) {
    asm("mov.b64 {%0, %1}, %2;" : "=f"(lo), "=f"(hi) : "l"(v));
}
__device__ __forceinline__ float hsum2(u64 v) {
    float lo, hi; unpack2(v, lo, hi); return lo + hi;
}

// Accurate-enough, overflow-safe activations (rel err ~2^-21 via MUFU)
__device__ __forceinline__ float sig_(float x) {
    return __fdividef(1.0f, 1.0f + __expf(-x));      // exp->inf  => 0   (ok)
}
__device__ __forceinline__ float tanh_(float x) {
    return __fdividef(2.0f, 1.0f + __expf(-2.0f * x)) - 1.0f;  // inf => -1 (ok)
}

// ---------------- kernel 0: prep (fused weights, transposes, flag reset) ---
__global__ void prep_kernel(const float* __restrict__ Wih0,
                            const float* __restrict__ Winp,
                            const float* __restrict__ binp,
                            const float* __restrict__ bih0,
                            const float* __restrict__ bhh0,
                            const float* __restrict__ Wout) {
    int tid = blockIdx.x * blockDim.x + threadIdx.x;
    if (tid < G4 * DIN) {                               // WcT[k][j] = sum_m Wih0[j,m]*Winp[m,k]
        int j = tid / DIN, k = tid % DIN;
        float s = 0.f;
        for (int m = 0; m < HID; m++)
            s = fmaf(Wih0[j * HID + m], Winp[m * DIN + k], s);
        g_WcT[k * G4 + j] = s;
    } else if (tid < G4 * DIN + G4) {                   // bc[j]
        int j = tid - G4 * DIN;
        float s = bih0[j] + bhh0[j];
        for (int m = 0; m < HID; m++)
            s = fmaf(Wih0[j * HID + m], binp[m], s);
        g_bc[j] = s;
    } else if (tid < G4 * DIN + G4 + DIN * HID) {       // WoutT[k][d]
        int q = tid - (G4 * DIN + G4);
        int d = q / HID, k = q % HID;
        g_WoutT[k * DIN + d] = Wout[d * HID + k];
    } else if (tid < G4 * DIN + G4 + DIN * HID + NCHUNK + 1) {
        int q = tid - (G4 * DIN + G4 + DIN * HID);
        if (q < NCHUNK) g_flag1[q] = 0;
        else            g_prog0 = 0;
    }
}

// ---------------- kernel 1: xp0 = inputs @ WcT + bc  (fully parallel) ------
__global__ __launch_bounds__(400) void xp0_gemm(const float* __restrict__ inputs) {
    __shared__ __align__(16) float inpT[DIN * 32];      // transposed tile [k][t]
    const int t0 = blockIdx.x * 32;
    const int j  = threadIdx.x;                         // 400 threads: one gate column each

    for (int idx = j; idx < 32 * DIN; idx += 400) {
        int t = idx / DIN, k = idx % DIN;
        inpT[k * 32 + t] = inputs[(t0 + t) * DIN + k];
    }
    __syncthreads();

    const float bcj = g_bc[j];
    u64 acc[16];
    #pragma unroll
    for (int tp = 0; tp < 16; tp++) acc[tp] = packf2(bcj, bcj);

    #pragma unroll 4
    for (int k = 0; k < DIN; k++) {
        float w = g_WcT[k * G4 + j];
        u64 w2 = packf2(w, w);
        const u64* row2 = (const u64*)(inpT + k * 32);
        #pragma unroll
        for (int tp = 0; tp < 16; tp++)
            acc[tp] = ffma2(w2, row2[tp], acc[tp]);
    }
    #pragma unroll
    for (int tp = 0; tp < 16; tp++) {
        float lo, hi; unpack2(acc[tp], lo, hi);
        g_xp0[(t0 + 2 * tp + 0) * G4 + j] = lo;
        g_xp0[(t0 + 2 * tp + 1) * G4 + j] = hi;
    }
}

// ---------------- persistent scan kernel -----------------------------------
// block 0: layer-0 scan | block 1: layer-1 scan | blocks 2..9: xp1 chasers
template <int L>
__device__ void layer_scan(const float* __restrict__ Whh,
                           const float* __restrict__ xp_src,
                           float* __restrict__ h_dst,
                           float* __restrict__ out) {
    __shared__ __align__(8) float hs[HID + 4];
    __shared__ float act[G4];
    const int j = threadIdx.x;                          // 400 threads

    // weights register-resident (float2-packed over k)
    u64 w[50];
    const float2* wrow = (const float2*)(Whh + j * HID);
    #pragma unroll
    for (int kk = 0; kk < 50; kk++) {
        float2 p = wrow[kk];
        w[kk] = packf2(p.x, p.y);
    }
    float c = 0.f;
    if (j < HID) hs[j] = 0.f;
    __syncthreads();

    const u64* h2 = (const u64*)hs;
    float xp_cur = 0.f, xp_nxt = 0.f;

    for (int t = 0; t < TT; t++) {
        if ((t & (CH - 1)) == 0) {
            if (L == 1) {                               // wait this chunk + next (covers prefetch)
                if (j == 0) {
                    int c0 = t >> 6;
                    int c1 = (c0 + 1 < NCHUNK) ? c0 + 1 : NCHUNK - 1;
                    while (g_flag1[c0] == 0 || g_flag1[c1] == 0) __nanosleep(128);
                    __threadfence();
                }
                __syncthreads();
            }
            if (t == 0) {                               // pipeline warmup
                xp_cur = xp_src[j];
                xp_nxt = xp_src[G4 + j];
            }
        }

        // recurrent matvec: gates[j] = sum_k Whh[j,k] * h[k]   (FFMA2, 2 chains)
        u64 a0 = 0ull, a1 = 0ull;
        #pragma unroll
        for (int kk = 0; kk < 50; kk += 2) {
            a0 = ffma2(w[kk],     h2[kk],     a0);
            a1 = ffma2(w[kk + 1], h2[kk + 1], a1);
        }
        // prefetch xp[t+2] (latency covered by ~2 steps)
        float xp_fut = (t + 2 < TT) ? xp_src[(t + 2) * G4 + j] : 0.f;

        float pre = xp_cur + (hsum2(a0) + hsum2(a1));
        float a = (j >= 200 && j < 300) ? tanh_(pre) : sig_(pre);   // i,f,o: sig; g: tanh
        act[j] = a;
        __syncthreads();

        if (j < HID) {
            float gi = act[j], gf = act[j + 100], gg = act[j + 200], go = act[j + 300];
            c = fmaf(gf, c, gi * gg);
            float h = go * tanh_(c);
            hs[j] = h;
            h_dst[t * HID + j] = h;
            if (L == 0 && ((t & (P0CH - 1)) == (P0CH - 1))) __threadfence();
        }
        __syncthreads();

        if (L == 0 && ((t & (P0CH - 1)) == (P0CH - 1)) && j == 0)
            g_prog0 = t + 1;

        xp_cur = xp_nxt;
        xp_nxt = xp_fut;
    }

    if (j < HID) {                                      // h_n / c_n tails
        out[TT * DIN + L * HID + j]        = hs[j];
        out[TT * DIN + 2 * HID + L * HID + j] = c;
    }
}

__device__ void chaser(int ci,
                       const float* __restrict__ Wih1,
                       const float* __restrict__ bih1,
                       const float* __restrict__ bhh1) {
    __shared__ __align__(8) float h0s[CH * HID];        // 25.6 KB
    const int j = threadIdx.x;

    u64 w[50];
    const float2* wrow = (const float2*)(Wih1 + j * HID);
    #pragma unroll
    for (int kk = 0; kk < 50; kk++) {
        float2 p = wrow[kk];
        w[kk] = packf2(p.x, p.y);
    }
    const float bj = bih1[j] + bhh1[j];
    const u64* h2 = (const u64*)h0s;

    for (int cidx = ci; cidx < NCHUNK; cidx += NCHASE) {
        const int t0 = cidx * CH;
        if (j == 0) {
            while (g_prog0 < t0 + CH) __nanosleep(256);
            __threadfence();
        }
        __syncthreads();
        for (int idx = j; idx < CH * HID; idx += G4)
            h0s[idx] = g_h0[t0 * HID + idx];
        __syncthreads();

        for (int t = 0; t < CH; t++) {
            u64 a0 = 0ull, a1 = 0ull;
            #pragma unroll
            for (int kk = 0; kk < 50; kk += 2) {
                a0 = ffma2(w[kk],     h2[t * 50 + kk],     a0);
                a1 = ffma2(w[kk + 1], h2[t * 50 + kk + 1], a1);
            }
            g_xp1[(t0 + t) * G4 + j] = bj + hsum2(a0) + hsum2(a1);
        }
        __threadfence();
        __syncthreads();
        if (j == 0) g_flag1[cidx] = 1;
    }
}

__global__ __launch_bounds__(400) void scan_kernel(const float* __restrict__ Whh0,
                                                   const float* __restrict__ Wih1,
                                                   const float* __restrict__ Whh1,
                                                   const float* __restrict__ bih1,
                                                   const float* __restrict__ bhh1,
                                                   float* __restrict__ out) {
    if (blockIdx.x == 0)      layer_scan<0>(Whh0, g_xp0, g_h0, out);
    else if (blockIdx.x == 1) layer_scan<1>(Whh1, g_xp1, g_h1, out);
    else                      chaser(blockIdx.x - 2, Wih1, bih1, bhh1);
}

// ---------------- kernel 3: outputs = h1_seq @ W_out^T + b_out -------------
__global__ __launch_bounds__(320) void out_gemm(const float* __restrict__ bout,
                                                float* __restrict__ out) {
    __shared__ __align__(8) float h1s[32 * HID];
    const int t0 = blockIdx.x * 32;
    const int d  = threadIdx.x;

    for (int idx = threadIdx.x; idx < 32 * HID; idx += 320)
        h1s[idx] = g_h1[t0 * HID + idx];
    __syncthreads();

    if (d < DIN) {
        u64 w[50];
        #pragma unroll
        for (int kk = 0; kk < 50; kk++)
            w[kk] = packf2(g_WoutT[(2 * kk) * DIN + d], g_WoutT[(2 * kk + 1) * DIN + d]);
        const float bd = bout[d];
        const u64* h2 = (const u64*)h1s;
        for (int t = 0; t < 32; t++) {
            u64 a0 = 0ull, a1 = 0ull;
            #pragma unroll
            for (int kk = 0; kk < 50; kk += 2) {
                a0 = ffma2(w[kk],     h2[t * 50 + kk],     a0);
                a1 = ffma2(w[kk + 1], h2[t * 50 + kk + 1], a1);
            }
            out[(t0 + t) * DIN + d] = bd + hsum2(a0) + hsum2(a1);
        }
    }
}

// ---------------- launch ----------------------------------------------------
extern "C" void kernel_launch(void* const* d_in, const int* in_sizes, int n_in,
                              void* d_out, int out_size) {
    (void)in_sizes; (void)n_in; (void)out_size;
    const float* inputs = (const float*)d_in[0];
    const float* W_inp  = (const float*)d_in[1];
    const float* b_inp  = (const float*)d_in[2];
    const float* Wih0   = (const float*)d_in[3];
    const float* Whh0   = (const float*)d_in[4];
    const float* bih0   = (const float*)d_in[5];
    const float* bhh0   = (const float*)d_in[6];
    const float* Wih1   = (const float*)d_in[7];
    const float* Whh1   = (const float*)d_in[8];
    const float* bih1   = (const float*)d_in[9];
    const float* bhh1   = (const float*)d_in[10];
    const float* Wout   = (const float*)d_in[11];
    const float* bout   = (const float*)d_in[12];
    float* out = (float*)d_out;

    prep_kernel<<<(G4 * DIN + G4 + DIN * HID + NCHUNK + 1 + 255) / 256, 256>>>(
        Wih0, W_inp, b_inp, bih0, bhh0, Wout);
    xp0_gemm<<<TT / 32, 400>>>(inputs);
    scan_kernel<<<2 + NCHASE, 400>>>(Whh0, Wih1, Whh1, bih1, bhh1, out);
    out_gemm<<<TT / 32, 320>>>(bout, out);
}